// round 1
// baseline (speedup 1.0000x reference)
#include <cuda_runtime.h>
#include <math_constants.h>

// GraphSAGE layer, fused: masked-max aggregation + relu + concat + Linear.
// B=4, N=512, C=128, OUT=128. adj ~10% dense (values 0.0/1.0 as float).
//
// Layout of work:
//   grid  = (B*N)/ROWS blocks, ROWS=8 rows per block
//   block = 256 threads = 8 warps
//   Phase 1 (aggregation): warp w owns row (block_row0 + w).
//     - copies its feature row into smem comb[w][0:128]
//     - scans adj row in 32-wide chunks, ballot-compacts nonzeros,
//       gathers float4 feature rows and running-maxes them
//     - neigh = fmaxf(acc, 0)  (handles both relu and the no-neighbor case,
//       since acc stays -inf / finfo.min-like when there are no neighbors)
//     - writes neigh into comb[w][128:256]
//   Phase 2 (GEMM): thread t -> output column o = t & 127, row group
//     r0 = (t>>7)*4. Each thread computes 4 rows x 1 column, loading W
//     scalar-coalesced (hits L1 after first pass) and comb via float4
//     broadcast LDS.

#define B_DIM 4
#define N_DIM 512
#define C_DIM 128
#define OUT_DIM 128
#define ROWS 8           // rows per block (== warps per block)
#define THREADS 256

__global__ __launch_bounds__(THREADS)
void graphsage_fused_kernel(const float* __restrict__ adj,
                            const float* __restrict__ feat,
                            const float* __restrict__ W,
                            const float* __restrict__ bias,
                            float* __restrict__ out)
{
    __shared__ __align__(16) float comb[ROWS][2 * C_DIM];

    const int block_row0 = blockIdx.x * ROWS;         // global row over B*N
    const int warp = threadIdx.x >> 5;
    const int lane = threadIdx.x & 31;

    // ---------------- Phase 1: aggregation (warp per row) ----------------
    {
        const int grow = block_row0 + warp;
        const int b = grow / N_DIM;
        const int i = grow % N_DIM;
        const float* __restrict__ adjrow = adj + ((size_t)b * N_DIM + i) * N_DIM;
        const float* __restrict__ fb = feat + (size_t)b * N_DIM * C_DIM;

        // copy own feature row into comb[warp][0:128]
        float4 myf = reinterpret_cast<const float4*>(fb + (size_t)i * C_DIM)[lane];
        reinterpret_cast<float4*>(&comb[warp][0])[lane] = myf;

        float4 acc = make_float4(-CUDART_INF_F, -CUDART_INF_F,
                                 -CUDART_INF_F, -CUDART_INF_F);

        #pragma unroll 4
        for (int chunk = 0; chunk < N_DIM; chunk += 32) {
            float a = adjrow[chunk + lane];
            unsigned m = __ballot_sync(0xffffffffu, a > 0.0f);
            while (m) {
                int bit = __ffs(m) - 1;
                m &= m - 1;
                int j = chunk + bit;
                float4 f = reinterpret_cast<const float4*>(fb + (size_t)j * C_DIM)[lane];
                acc.x = fmaxf(acc.x, f.x);
                acc.y = fmaxf(acc.y, f.y);
                acc.z = fmaxf(acc.z, f.z);
                acc.w = fmaxf(acc.w, f.w);
            }
        }

        // relu + no-neighbor handling in one op
        float4 nb;
        nb.x = fmaxf(acc.x, 0.0f);
        nb.y = fmaxf(acc.y, 0.0f);
        nb.z = fmaxf(acc.z, 0.0f);
        nb.w = fmaxf(acc.w, 0.0f);
        reinterpret_cast<float4*>(&comb[warp][C_DIM])[lane] = nb;
    }

    __syncthreads();

    // ---------------- Phase 2: fused linear layer ----------------
    {
        const int o  = threadIdx.x & (OUT_DIM - 1);
        const int r0 = (threadIdx.x >> 7) * 4;

        const float bv = bias[o];
        float a0 = bv, a1 = bv, a2 = bv, a3 = bv;

        const float4* __restrict__ c0 = reinterpret_cast<const float4*>(comb[r0 + 0]);
        const float4* __restrict__ c1 = reinterpret_cast<const float4*>(comb[r0 + 1]);
        const float4* __restrict__ c2 = reinterpret_cast<const float4*>(comb[r0 + 2]);
        const float4* __restrict__ c3 = reinterpret_cast<const float4*>(comb[r0 + 3]);

        #pragma unroll 4
        for (int c4 = 0; c4 < (2 * C_DIM) / 4; ++c4) {
            float4 f0 = c0[c4];
            float4 f1 = c1[c4];
            float4 f2 = c2[c4];
            float4 f3 = c3[c4];
            const float* __restrict__ wp = W + (size_t)c4 * 4 * OUT_DIM + o;
            float w0 = wp[0 * OUT_DIM];
            float w1 = wp[1 * OUT_DIM];
            float w2 = wp[2 * OUT_DIM];
            float w3 = wp[3 * OUT_DIM];

            a0 += f0.x * w0; a0 += f0.y * w1; a0 += f0.z * w2; a0 += f0.w * w3;
            a1 += f1.x * w0; a1 += f1.y * w1; a1 += f1.z * w2; a1 += f1.w * w3;
            a2 += f2.x * w0; a2 += f2.y * w1; a2 += f2.z * w2; a2 += f2.w * w3;
            a3 += f3.x * w0; a3 += f3.y * w1; a3 += f3.z * w2; a3 += f3.w * w3;
        }

        const size_t orow = (size_t)(block_row0 + r0);
        out[(orow + 0) * OUT_DIM + o] = a0;
        out[(orow + 1) * OUT_DIM + o] = a1;
        out[(orow + 2) * OUT_DIM + o] = a2;
        out[(orow + 3) * OUT_DIM + o] = a3;
    }
}

extern "C" void kernel_launch(void* const* d_in, const int* in_sizes, int n_in,
                              void* d_out, int out_size)
{
    (void)in_sizes; (void)n_in; (void)out_size;
    const float* adj  = (const float*)d_in[0];   // [B,N,N]
    const float* feat = (const float*)d_in[1];   // [B,N,C]
    const float* W    = (const float*)d_in[2];   // [2C,OUT]
    const float* bias = (const float*)d_in[3];   // [OUT]
    float* out        = (float*)d_out;           // [B,N,OUT]

    dim3 grid((B_DIM * N_DIM) / ROWS);
    dim3 block(THREADS);
    graphsage_fused_kernel<<<grid, block>>>(adj, feat, W, bias, out);
}

// round 2
// speedup vs baseline: 1.4581x; 1.4581x over previous
#include <cuda_runtime.h>
#include <math_constants.h>

// GraphSAGE fused: masked-max aggregation + relu + concat + Linear.
// B=4, N=512, C=128, OUT=128, adj ~10% dense (0.0/1.0 floats).
//
// R2 changes vs R1:
//  - 2 warps per row (each scans half the adjacency row) -> 2x warps, occ up
//  - neighbor indices ballot-compacted into SMEM, then gathered in batches
//    of 8 independent LDG.128s (MLP=8) into 4 rotating accumulators
//  - tail removed by padding index list with duplicate of last index
//    (max is idempotent)
//  - GEMM phase: 512 threads, 2 rows x 1 col each

#define B_DIM 4
#define N_DIM 512
#define C_DIM 128
#define OUT_DIM 128
#define ROWS 8            // rows per block
#define THREADS 512       // 16 warps: 2 per row

__global__ __launch_bounds__(THREADS)
void graphsage_fused_kernel(const float* __restrict__ adj,
                            const float* __restrict__ feat,
                            const float* __restrict__ W,
                            const float* __restrict__ bias,
                            float* __restrict__ out)
{
    __shared__ __align__(16) float comb[ROWS][2 * C_DIM];            // 8 KB
    __shared__ __align__(16) float aggbuf[ROWS][2][C_DIM];           // 8 KB
    __shared__ __align__(16) unsigned short idxbuf[16][272];         // 8.5 KB

    const int tid  = threadIdx.x;
    const int warp = tid >> 5;         // 0..15
    const int lane = tid & 31;
    const int row  = warp >> 1;        // 0..7 (row within block)
    const int half = warp & 1;         // which half of the adjacency row

    const int block_row0 = blockIdx.x * ROWS;
    const int grow = block_row0 + row;
    const int b = grow / N_DIM;
    const int i = grow % N_DIM;

    const float* __restrict__ fb = feat + (size_t)b * N_DIM * C_DIM;

    // ---------------- Phase 1a: own-feature copy ----------------
    if (half == 0) {
        float4 myf = reinterpret_cast<const float4*>(fb + (size_t)i * C_DIM)[lane];
        reinterpret_cast<float4*>(&comb[row][0])[lane] = myf;
    }

    // ---------------- Phase 1b: compact neighbor indices ----------------
    const float* __restrict__ adjrow =
        adj + ((size_t)b * N_DIM + i) * N_DIM + half * (N_DIM / 2);
    unsigned short* __restrict__ myidx = idxbuf[warp];
    const unsigned lt = (1u << lane) - 1u;

    int total = 0;
    #pragma unroll
    for (int c = 0; c < N_DIM / 2; c += 128) {
        float4 a = reinterpret_cast<const float4*>(adjrow + c)[lane];
        const int cbase = half * (N_DIM / 2) + c + 4 * lane;
        {
            unsigned m = __ballot_sync(0xffffffffu, a.x > 0.0f);
            if (a.x > 0.0f) myidx[total + __popc(m & lt)] = (unsigned short)(cbase + 0);
            total += __popc(m);
        }
        {
            unsigned m = __ballot_sync(0xffffffffu, a.y > 0.0f);
            if (a.y > 0.0f) myidx[total + __popc(m & lt)] = (unsigned short)(cbase + 1);
            total += __popc(m);
        }
        {
            unsigned m = __ballot_sync(0xffffffffu, a.z > 0.0f);
            if (a.z > 0.0f) myidx[total + __popc(m & lt)] = (unsigned short)(cbase + 2);
            total += __popc(m);
        }
        {
            unsigned m = __ballot_sync(0xffffffffu, a.w > 0.0f);
            if (a.w > 0.0f) myidx[total + __popc(m & lt)] = (unsigned short)(cbase + 3);
            total += __popc(m);
        }
    }
    __syncwarp();

    // ---------------- Phase 1c: gather + running max, MLP=8 ----------------
    float4 acc0 = make_float4(-CUDART_INF_F, -CUDART_INF_F, -CUDART_INF_F, -CUDART_INF_F);
    float4 acc1 = acc0, acc2 = acc0, acc3 = acc0;

    if (total > 0) {
        // pad to multiple of 8 with duplicate of last index (max is idempotent)
        const int padded = (total + 7) & ~7;
        unsigned short lastv = myidx[total - 1];
        __syncwarp();
        if (lane < padded - total) myidx[total + lane] = lastv;
        __syncwarp();

        const uint4* __restrict__ ivec = reinterpret_cast<const uint4*>(myidx);
        for (int k = 0; k < padded; k += 8) {
            uint4 I = ivec[k >> 3];
            int j0 =  I.x        & 0xffff;
            int j1 = (I.x >> 16) & 0xffff;
            int j2 =  I.y        & 0xffff;
            int j3 = (I.y >> 16) & 0xffff;
            int j4 =  I.z        & 0xffff;
            int j5 = (I.z >> 16) & 0xffff;
            int j6 =  I.w        & 0xffff;
            int j7 = (I.w >> 16) & 0xffff;

            float4 f0 = reinterpret_cast<const float4*>(fb + (size_t)j0 * C_DIM)[lane];
            float4 f1 = reinterpret_cast<const float4*>(fb + (size_t)j1 * C_DIM)[lane];
            float4 f2 = reinterpret_cast<const float4*>(fb + (size_t)j2 * C_DIM)[lane];
            float4 f3 = reinterpret_cast<const float4*>(fb + (size_t)j3 * C_DIM)[lane];
            float4 f4 = reinterpret_cast<const float4*>(fb + (size_t)j4 * C_DIM)[lane];
            float4 f5 = reinterpret_cast<const float4*>(fb + (size_t)j5 * C_DIM)[lane];
            float4 f6 = reinterpret_cast<const float4*>(fb + (size_t)j6 * C_DIM)[lane];
            float4 f7 = reinterpret_cast<const float4*>(fb + (size_t)j7 * C_DIM)[lane];

            acc0.x = fmaxf(acc0.x, f0.x); acc0.y = fmaxf(acc0.y, f0.y);
            acc0.z = fmaxf(acc0.z, f0.z); acc0.w = fmaxf(acc0.w, f0.w);
            acc1.x = fmaxf(acc1.x, f1.x); acc1.y = fmaxf(acc1.y, f1.y);
            acc1.z = fmaxf(acc1.z, f1.z); acc1.w = fmaxf(acc1.w, f1.w);
            acc2.x = fmaxf(acc2.x, f2.x); acc2.y = fmaxf(acc2.y, f2.y);
            acc2.z = fmaxf(acc2.z, f2.z); acc2.w = fmaxf(acc2.w, f2.w);
            acc3.x = fmaxf(acc3.x, f3.x); acc3.y = fmaxf(acc3.y, f3.y);
            acc3.z = fmaxf(acc3.z, f3.z); acc3.w = fmaxf(acc3.w, f3.w);

            acc0.x = fmaxf(acc0.x, f4.x); acc0.y = fmaxf(acc0.y, f4.y);
            acc0.z = fmaxf(acc0.z, f4.z); acc0.w = fmaxf(acc0.w, f4.w);
            acc1.x = fmaxf(acc1.x, f5.x); acc1.y = fmaxf(acc1.y, f5.y);
            acc1.z = fmaxf(acc1.z, f5.z); acc1.w = fmaxf(acc1.w, f5.w);
            acc2.x = fmaxf(acc2.x, f6.x); acc2.y = fmaxf(acc2.y, f6.y);
            acc2.z = fmaxf(acc2.z, f6.z); acc2.w = fmaxf(acc2.w, f6.w);
            acc3.x = fmaxf(acc3.x, f7.x); acc3.y = fmaxf(acc3.y, f7.y);
            acc3.z = fmaxf(acc3.z, f7.z); acc3.w = fmaxf(acc3.w, f7.w);
        }
    }

    float4 accA;
    accA.x = fmaxf(fmaxf(acc0.x, acc1.x), fmaxf(acc2.x, acc3.x));
    accA.y = fmaxf(fmaxf(acc0.y, acc1.y), fmaxf(acc2.y, acc3.y));
    accA.z = fmaxf(fmaxf(acc0.z, acc1.z), fmaxf(acc2.z, acc3.z));
    accA.w = fmaxf(fmaxf(acc0.w, acc1.w), fmaxf(acc2.w, acc3.w));
    reinterpret_cast<float4*>(&aggbuf[row][half][0])[lane] = accA;

    __syncthreads();

    // ---------------- Phase 1d: combine halves + relu ----------------
    #pragma unroll
    for (int t = tid; t < ROWS * C_DIM; t += THREADS) {
        int r = t >> 7;
        int c = t & (C_DIM - 1);
        comb[r][C_DIM + c] = fmaxf(0.0f, fmaxf(aggbuf[r][0][c], aggbuf[r][1][c]));
    }
    __syncthreads();

    // ---------------- Phase 2: fused linear layer ----------------
    {
        const int o  = tid & (OUT_DIM - 1);
        const int r0 = (tid >> 7) * 2;     // 4 groups of 2 rows

        const float bv = bias[o];
        float a0 = bv, a1 = bv;

        const float4* __restrict__ c0 = reinterpret_cast<const float4*>(comb[r0 + 0]);
        const float4* __restrict__ c1 = reinterpret_cast<const float4*>(comb[r0 + 1]);

        #pragma unroll 8
        for (int c4 = 0; c4 < (2 * C_DIM) / 4; ++c4) {
            float4 f0 = c0[c4];
            float4 f1 = c1[c4];
            const float* __restrict__ wp = W + (size_t)c4 * 4 * OUT_DIM + o;
            float w0 = wp[0 * OUT_DIM];
            float w1 = wp[1 * OUT_DIM];
            float w2 = wp[2 * OUT_DIM];
            float w3 = wp[3 * OUT_DIM];

            a0 += f0.x * w0; a0 += f0.y * w1; a0 += f0.z * w2; a0 += f0.w * w3;
            a1 += f1.x * w0; a1 += f1.y * w1; a1 += f1.z * w2; a1 += f1.w * w3;
        }

        const size_t orow = (size_t)(block_row0 + r0);
        out[(orow + 0) * OUT_DIM + o] = a0;
        out[(orow + 1) * OUT_DIM + o] = a1;
    }
}

extern "C" void kernel_launch(void* const* d_in, const int* in_sizes, int n_in,
                              void* d_out, int out_size)
{
    (void)in_sizes; (void)n_in; (void)out_size;
    const float* adj  = (const float*)d_in[0];   // [B,N,N]
    const float* feat = (const float*)d_in[1];   // [B,N,C]
    const float* W    = (const float*)d_in[2];   // [2C,OUT]
    const float* bias = (const float*)d_in[3];   // [OUT]
    float* out        = (float*)d_out;           // [B,N,OUT]

    dim3 grid((B_DIM * N_DIM) / ROWS);
    dim3 block(THREADS);
    graphsage_fused_kernel<<<grid, block>>>(adj, feat, W, bias, out);
}